// round 1
// baseline (speedup 1.0000x reference)
#include <cuda_runtime.h>

#define BATCH 2
#define NV    4096
#define NF    4096
#define IMG_H 256
#define IMG_W 256

// Scratch (no device allocation allowed in kernel_launch)
__device__ float2 g_ndc[BATCH * NV];        // per-vertex ndc x,y
__device__ float4 g_tri[BATCH * NF * 2];    // per-tri: (x0,y0,x1,y1),(x2,y2,_,_)

// ---------------------------------------------------------------------------
// Kernel 1: vertex transform -> NDC (x,y only; z never affects the mask)
// ---------------------------------------------------------------------------
__global__ void vert_kernel(const float* __restrict__ verts,
                            const float* __restrict__ Rm,
                            const float* __restrict__ Tm) {
    int idx = blockIdx.x * blockDim.x + threadIdx.x;
    if (idx >= BATCH * NV) return;
    int b = idx / NV;

    const float* R = Rm + b * 9;   // row-major R[i][j] = R[i*3+j]
    const float* T = Tm + b * 3;

    // Rt[i][j] = R[j][i];  t = -Rt @ T  (reference summation order j=0,1,2)
    float t0 = -((R[0] * T[0] + R[3] * T[1]) + R[6] * T[2]);
    float t1 = -((R[1] * T[0] + R[4] * T[1]) + R[7] * T[2]);
    float t2 = -((R[2] * T[0] + R[5] * T[1]) + R[8] * T[2]);

    // projection constants (fp64 -> fp32, matching jnp.array(..., float32))
    const float f   = 1.7320508075688772f;     // 1/tan(30 deg)
    const float p22 = -1.0020020020020020f;    // (FAR+NEAR)/(NEAR-FAR)
    const float p23 = -0.0200200200200200f;    // 2*FAR*NEAR/(NEAR-FAR)
    (void)p22; (void)p23;                      // z row unused for the mask

    // VP = proj @ w2c, formed entrywise first (reference order), then dot.
    float VP00 = f * R[0], VP01 = f * R[3], VP02 = f * R[6], VP03 = f * t0;
    float VP10 = f * R[1], VP11 = f * R[4], VP12 = f * R[7], VP13 = f * t1;
    float VP30 = -R[2],    VP31 = -R[5],    VP32 = -R[8],    VP33 = -t2;

    float v0 = verts[idx * 3 + 0];
    float v1 = verts[idx * 3 + 1];
    float v2 = verts[idx * 3 + 2];

    float cam0 = ((v0 * VP00 + v1 * VP01) + v2 * VP02) + VP03;
    float cam1 = ((v0 * VP10 + v1 * VP11) + v2 * VP12) + VP13;
    float cam3 = ((v0 * VP30 + v1 * VP31) + v2 * VP32) + VP33;

    float w = fmaxf(cam3, 1e-8f);
    g_ndc[idx] = make_float2(cam0 / w, cam1 / w);
}

// ---------------------------------------------------------------------------
// Kernel 2: gather per-triangle screen coords into contiguous float4 pairs
// ---------------------------------------------------------------------------
__global__ void setup_kernel(const int* __restrict__ faces) {
    int idx = blockIdx.x * blockDim.x + threadIdx.x;
    if (idx >= BATCH * NF) return;
    int b = idx / NF;
    int base = b * NV;

    int i0 = faces[idx * 3 + 0];
    int i1 = faces[idx * 3 + 1];
    int i2 = faces[idx * 3 + 2];

    float2 p0 = g_ndc[base + i0];
    float2 p1 = g_ndc[base + i1];
    float2 p2 = g_ndc[base + i2];

    g_tri[idx * 2 + 0] = make_float4(p0.x, p0.y, p1.x, p1.y);
    g_tri[idx * 2 + 1] = make_float4(p2.x, p2.y, 0.0f, 0.0f);
}

// ---------------------------------------------------------------------------
// Kernel 3: per-pixel coverage with early exit (mask = OR over triangles)
// ---------------------------------------------------------------------------
__global__ void raster_kernel(float* __restrict__ out) {
    int pix = blockIdx.x * blockDim.x + threadIdx.x;
    if (pix >= BATCH * IMG_H * IMG_W) return;

    int b = pix / (IMG_H * IMG_W);
    int r = pix - b * (IMG_H * IMG_W);
    int y = r / IMG_W;
    int x = r - y * IMG_W;

    // same expression order as reference: ((i+0.5)/N)*2 - 1
    float px = (((float)x + 0.5f) / (float)IMG_W) * 2.0f - 1.0f;
    float py = (((float)y + 0.5f) / (float)IMG_H) * 2.0f - 1.0f;

    const float4* tri = g_tri + b * NF * 2;

    float covered = 0.0f;
    #pragma unroll 4
    for (int t = 0; t < NF; ++t) {
        float4 A = __ldg(&tri[t * 2 + 0]);   // x0,y0,x1,y1
        float4 C = __ldg(&tri[t * 2 + 1]);   // x2,y2

        float e0 = (A.z - A.x) * (py - A.y) - (A.w - A.y) * (px - A.x);
        float e1 = (C.x - A.z) * (py - A.w) - (C.y - A.w) * (px - A.z);
        float e2 = (A.x - C.x) * (py - C.y) - (A.y - C.y) * (px - C.x);

        bool pos = (e0 >= 0.0f) & (e1 >= 0.0f) & (e2 >= 0.0f);
        bool neg = (e0 <= 0.0f) & (e1 <= 0.0f) & (e2 <= 0.0f);
        if (pos | neg) { covered = 1.0f; break; }
    }

    float* o = out + (size_t)pix * 3;
    o[0] = covered;
    o[1] = covered;
    o[2] = covered;
}

// ---------------------------------------------------------------------------
extern "C" void kernel_launch(void* const* d_in, const int* in_sizes, int n_in,
                              void* d_out, int out_size) {
    const float* verts = (const float*)d_in[0];   // [2,4096,3]
    const int*   faces = (const int*)  d_in[1];   // [2,4096,3]
    const float* Rm    = (const float*)d_in[2];   // [2,3,3]
    const float* Tm    = (const float*)d_in[3];   // [2,3]
    float* out = (float*)d_out;                   // [2,256,256,3]

    vert_kernel<<<(BATCH * NV + 255) / 256, 256>>>(verts, Rm, Tm);
    setup_kernel<<<(BATCH * NF + 255) / 256, 256>>>(faces);
    raster_kernel<<<(BATCH * IMG_H * IMG_W + 255) / 256, 256>>>(out);
}